// round 3
// baseline (speedup 1.0000x reference)
#include <cuda_runtime.h>
#include <cstdint>

#define N_NODES 64
#define N_EDGES 512
#define N_ACT   16
#define ITERS   8
#define N_BATCH 512

static constexpr float INV_E = 1.0f / 512.0f;
static constexpr float INV_N = 1.0f / 64.0f;
static constexpr float INV_A = 1.0f / 16.0f;

// -------- adjacency (batch-independent), built deterministically per launch --------
__device__ int g_in_start[N_NODES + 1];
__device__ int g_out_start[N_NODES + 1];
__device__ int g_in_list[N_EDGES];
__device__ int g_out_list[N_EDGES];

__global__ void DCG_prep_kernel(const int* __restrict__ ef_g, const int* __restrict__ et_g) {
    __shared__ int sf[N_EDGES], st[N_EDGES];
    __shared__ int cin[N_NODES], cout[N_NODES];
    int tid = threadIdx.x;
    for (int e = tid; e < N_EDGES; e += blockDim.x) { sf[e] = ef_g[e]; st[e] = et_g[e]; }
    __syncthreads();
    if (tid < N_NODES) {
        int n = tid, c = 0;
        for (int e = 0; e < N_EDGES; e++) if (st[e] == n) c++;
        cin[n] = c;
    } else if (tid < 2 * N_NODES) {
        int n = tid - N_NODES, c = 0;
        for (int e = 0; e < N_EDGES; e++) if (sf[e] == n) c++;
        cout[n] = c;
    }
    __syncthreads();
    if (tid == 0) {
        int s = 0;
        for (int n = 0; n < N_NODES; n++) { g_in_start[n] = s; s += cin[n]; }
        g_in_start[N_NODES] = s;
    } else if (tid == 1) {
        int s = 0;
        for (int n = 0; n < N_NODES; n++) { g_out_start[n] = s; s += cout[n]; }
        g_out_start[N_NODES] = s;
    }
    __syncthreads();
    // fill lists in ascending edge order (deterministic summation order later)
    if (tid < N_NODES) {
        int n = tid, p = g_in_start[n];
        for (int e = 0; e < N_EDGES; e++) if (st[e] == n) g_in_list[p++] = e;
    } else if (tid < 2 * N_NODES) {
        int n = tid - N_NODES, p = g_out_start[n];
        for (int e = 0; e < N_EDGES; e++) if (sf[e] == n) g_out_list[p++] = e;
    }
}

// -------- shared memory layout (floats) --------
// OFF_Q0   = 0      (1024)
// OFF_Q    = 1024   (1024)
// OFF_MF   = 2048   (8192)
// OFF_MB   = 10240  (8192)
// OFF_NVS  = 18432  (1024)  raw node_vals
// OFF_TILE = 19456  (32 warps * 272)   (also reused as eval staging, 512 floats)
// OFF_CFCT = 28160  (32 warps * 32)
// OFF_QMAX = 29184  (2 slots: qmax, qv broadcast)
// int section @ float index 29186: ef 512 | et 512 | ins 65 | outs 65 | inl 512 | outl 512 | a_cur 64 | a_best 64 | flag 1
static constexpr int SMEM_FLOATS = 29186;
static constexpr int SMEM_INTS   = 2307;
static constexpr int SMEM_BYTES  = (SMEM_FLOATS + SMEM_INTS) * 4;  // 125,972 B -> 1 CTA/SM

__global__ __launch_bounds__(1024, 1)
void DCG_main_kernel(const float* __restrict__ node_vals,
                     const float* __restrict__ edge_vals,
                     const int* __restrict__ ef_g,
                     const int* __restrict__ et_g,
                     float* __restrict__ out) {
    extern __shared__ float sm[];
    float* q0    = sm;
    float* q     = sm + 1024;
    float* mf    = sm + 2048;
    float* mb    = sm + 10240;
    float* nvs   = sm + 18432;   // raw node_vals
    float* tiles = sm + 19456;   // phase-1 tiles; reused as eval edge staging
    float* cfct  = sm + 28160;
    float* s_qmax = sm + 29184;  // [0]=qmax, [1]=last eval value
    int* si      = (int*)(sm + 29186);
    int* ef      = si;
    int* et      = si + 512;
    int* ins     = si + 1024;
    int* outs    = si + 1089;
    int* inl     = si + 1154;
    int* outl    = si + 1666;
    int* a_cur   = si + 2178;
    int* a_best  = si + 2242;
    int* s_flag  = si + 2306;

    const int tid  = threadIdx.x;
    const int b    = blockIdx.x;
    const int warp = tid >> 5;
    const int lane = tid & 31;
    const int j    = lane & 15;
    const int half = lane >> 4;

    // ---- load static data to SMEM ----
    for (int i = tid; i < N_EDGES; i += 1024) {
        ef[i]   = ef_g[i];
        et[i]   = et_g[i];
        inl[i]  = g_in_list[i];
        outl[i] = g_out_list[i];
    }
    if (tid < N_NODES + 1) { ins[tid] = g_in_start[tid]; outs[tid] = g_out_start[tid]; }

    const float* nv = node_vals + (size_t)b * (N_NODES * N_ACT);
    {
        float raw = nv[tid];
        nvs[tid] = raw;
        float v = raw * INV_N;   // exact (power of two)
        q0[tid] = v;
        q[tid]  = v;
    }
    for (int i = tid; i < N_EDGES * N_ACT; i += 1024) { mf[i] = 0.0f; mb[i] = 0.0f; }
    __syncthreads();

    // ---- initial action: argmax(node_vals) (first-max like jnp.argmax) ----
    if (tid < N_NODES) {
        const float* row = nvs + tid * N_ACT;
        int best = 0; float bv = row[0];
        #pragma unroll
        for (int a = 1; a < N_ACT; a++) { float v = row[a]; if (v > bv) { bv = v; best = a; } }
        a_cur[tid]  = best;
        a_best[tid] = best;
    }
    __syncthreads();

    const float* ebase = edge_vals + (size_t)b * (N_EDGES * N_ACT * N_ACT);

    // eval of a_cur, matching jax/XLA-CPU strict in-order reduction:
    //   node_sum = sum_{n=0..63} node_vals[n, a_cur[n]]   (left-to-right)
    //   edge_sum = sum_{e=0..511} edge_vals[e, af, at]    (left-to-right)
    //   qv = node_sum/64 + edge_sum/512
    auto eval_action = [&]() -> float {
        if (tid < N_EDGES) {
            int af = a_cur[ef[tid]], at = a_cur[et[tid]];
            tiles[tid] = ebase[(size_t)tid * 256 + af * 16 + at];
        }
        __syncthreads();
        if (tid == 0) {
            float es = 0.0f;
            #pragma unroll 8
            for (int e = 0; e < N_EDGES; e++) es += tiles[e];
            float ns = 0.0f;
            #pragma unroll 8
            for (int n = 0; n < N_NODES; n++) ns += nvs[n * N_ACT + a_cur[n]];
            s_qmax[1] = ns * INV_N + es * INV_E;
        }
        __syncthreads();
        return s_qmax[1];
    };

    {
        float qv = eval_action();
        if (tid == 0) s_qmax[0] = qv;
    }
    __syncthreads();

    // ================= message-passing iterations =================
    for (int it = 0; it < ITERS; it++) {
        // ---- phase 1: per-edge messages (warp per edge, 16 edges/warp) ----
        float* tw   = tiles + warp * 272;
        float* crow = cfct + warp * 32 + half * 16;
        for (int k = 0; k < 16; k++) {
            int e  = k * 32 + warp;
            int fn = ef[e], tn = et[e];
            // c: lanes 0-15 -> cf[j] = q[from,j] - mb[e,j]; lanes 16-31 -> ct[j] = q[to,j] - mf[e,j]
            float c;
            if (half == 0) c = q[fn * N_ACT + j] - mb[e * N_ACT + j];
            else           c = q[tn * N_ACT + j] - mf[e * N_ACT + j];
            cfct[warp * 32 + lane] = c;

            // stage 16x16 tile -> padded (stride 17) SMEM; 2 coalesced float4 per lane
            const float4* src = (const float4*)(ebase + (size_t)e * 256);
            float4 v0 = src[lane];
            float4 v1 = src[lane + 32];
            int k0  = lane * 4;
            int r0  = (k0 >> 4) * 17 + (k0 & 15);
            tw[r0 + 0] = v0.x; tw[r0 + 1] = v0.y; tw[r0 + 2] = v0.z; tw[r0 + 3] = v0.w;
            int k1  = k0 + 128;
            int r1  = (k1 >> 4) * 17 + (k1 & 15);
            tw[r1 + 0] = v1.x; tw[r1 + 1] = v1.y; tw[r1 + 2] = v1.z; tw[r1 + 3] = v1.w;
            __syncwarp();

            // mf_new[j] = max_i (cf[i] + T[i][j]/E) ; mb_new[j] = max_i (ct[i] + T[j][i]/E)
            // (t*INV_E is exact power-of-two scaling, so fma == add of T/E bitwise)
            float m = -3.402823466e38f;
            #pragma unroll
            for (int i = 0; i < 16; i++) {
                float t = half ? tw[j * 17 + i] : tw[i * 17 + j];
                m = fmaxf(m, fmaf(t, INV_E, crow[i]));
            }

            // subtract mean over 16 actions — STRICT in-order sequential sum (XLA-CPU order)
            {
                float v[16];
                #pragma unroll
                for (int i = 0; i < 16; i++)
                    v[i] = __shfl_sync(0xffffffffu, m, (half << 4) + i);
                float ssum = v[0];
                #pragma unroll
                for (int i = 1; i < 16; i++) ssum += v[i];
                m = m - ssum * INV_A;   // == m - sum/16 (exact scale)
            }

            if (half == 0) mf[e * N_ACT + j] = m;
            else           mb[e * N_ACT + j] = m;
            __syncwarp();   // protect tiles/cfct before next k overwrites
        }
        __syncthreads();

        // ---- phase 2: q = q0 + scatter(mf by to) + scatter(mb by from) ----
        // ascending edge order, all mf first then all mb (matches .at[].add order)
        {
            int n = tid >> 4, a = tid & 15;
            float acc = q0[tid];
            int s0 = ins[n], s1 = ins[n + 1];
            for (int kk = s0; kk < s1; kk++) acc += mf[inl[kk] * N_ACT + a];
            s0 = outs[n]; s1 = outs[n + 1];
            for (int kk = s0; kk < s1; kk++) acc += mb[outl[kk] * N_ACT + a];
            q[tid] = acc;
        }
        __syncthreads();

        // ---- phase 3: argmax + eval + best-so-far ----
        if (tid < N_NODES) {
            const float* row = q + tid * N_ACT;
            int best = 0; float bv = row[0];
            #pragma unroll
            for (int a = 1; a < N_ACT; a++) { float v = row[a]; if (v > bv) { bv = v; best = a; } }
            a_cur[tid] = best;
        }
        __syncthreads();
        float qvi = eval_action();
        if (tid == 0) {
            if (qvi > s_qmax[0]) { s_qmax[0] = qvi; *s_flag = 1; }
            else                 { *s_flag = 0; }
        }
        __syncthreads();
        if (*s_flag && tid < N_NODES) a_best[tid] = a_cur[tid];
        __syncthreads();
    }

    // ---- output: q_max[512] then a_max[512*64] (as float) ----
    if (tid == 0) out[b] = s_qmax[0];
    if (tid < N_NODES) out[N_BATCH + b * N_NODES + tid] = (float)a_best[tid];
}

extern "C" void kernel_launch(void* const* d_in, const int* in_sizes, int n_in,
                              void* d_out, int out_size) {
    const float* node_vals = (const float*)d_in[0];
    const float* edge_vals = (const float*)d_in[1];
    const int*   ef        = (const int*)d_in[2];
    const int*   et        = (const int*)d_in[3];
    float*       out       = (float*)d_out;

    static bool attr_set = false;
    if (!attr_set) {
        cudaFuncSetAttribute(DCG_main_kernel,
                             cudaFuncAttributeMaxDynamicSharedMemorySize, SMEM_BYTES);
        attr_set = true;
    }

    DCG_prep_kernel<<<1, 128>>>(ef, et);
    DCG_main_kernel<<<N_BATCH, 1024, SMEM_BYTES>>>(node_vals, edge_vals, ef, et, out);
}

// round 4
// speedup vs baseline: 2.1949x; 2.1949x over previous
#include <cuda_runtime.h>
#include <cstdint>

#define N_NODES 64
#define N_EDGES 512
#define N_ACT   16
#define ITERS   8
#define N_BATCH 512
#define MSG_STRIDE 17   // padded row stride for mf/mb (bank-conflict-free column access)

static constexpr float INV_E = 1.0f / 512.0f;
static constexpr float INV_N = 1.0f / 64.0f;
static constexpr float INV_A = 1.0f / 16.0f;

// -------- adjacency (batch-independent), built deterministically per launch --------
__device__ int g_in_start[N_NODES + 1];
__device__ int g_out_start[N_NODES + 1];
__device__ int g_in_list[N_EDGES];
__device__ int g_out_list[N_EDGES];

__global__ void DCG_prep_kernel(const int* __restrict__ ef_g, const int* __restrict__ et_g) {
    __shared__ int sf[N_EDGES], st[N_EDGES];
    __shared__ int cin[N_NODES], cout[N_NODES];
    int tid = threadIdx.x;
    for (int e = tid; e < N_EDGES; e += blockDim.x) { sf[e] = ef_g[e]; st[e] = et_g[e]; }
    __syncthreads();
    if (tid < N_NODES) {
        int n = tid, c = 0;
        for (int e = 0; e < N_EDGES; e++) if (st[e] == n) c++;
        cin[n] = c;
    } else if (tid < 2 * N_NODES) {
        int n = tid - N_NODES, c = 0;
        for (int e = 0; e < N_EDGES; e++) if (sf[e] == n) c++;
        cout[n] = c;
    }
    __syncthreads();
    if (tid == 0) {
        int s = 0;
        for (int n = 0; n < N_NODES; n++) { g_in_start[n] = s; s += cin[n]; }
        g_in_start[N_NODES] = s;
    } else if (tid == 1) {
        int s = 0;
        for (int n = 0; n < N_NODES; n++) { g_out_start[n] = s; s += cout[n]; }
        g_out_start[N_NODES] = s;
    }
    __syncthreads();
    if (tid < N_NODES) {
        int n = tid, p = g_in_start[n];
        for (int e = 0; e < N_EDGES; e++) if (st[e] == n) g_in_list[p++] = e;
    } else if (tid < 2 * N_NODES) {
        int n = tid - N_NODES, p = g_out_start[n];
        for (int e = 0; e < N_EDGES; e++) if (sf[e] == n) g_out_list[p++] = e;
    }
}

// -------- shared memory layout --------
// floats:
//   q0   @ 0      (1024)
//   q    @ 1024   (1024)
//   nvs  @ 2048   (1024)   raw node_vals
//   mf   @ 3072   (512*17 = 8704)
//   pad  @ 11776  (16)     -> mb bank base offset 16 vs mf (disjoint half-banks)
//   mb   @ 11792  (8704)
//   evs  @ 20496  (9*512 = 4608)   deferred-eval staging
//   qv   @ 25104  (16)
//   aux  @ 25120  (2)
// ints @ float index 25122:
//   ef 512 | et 512 | ins 65 | outs 65 | inl 512 | outl 512 | a_hist 9*64=576 | bc 1
static constexpr int OFF_Q0  = 0;
static constexpr int OFF_Q   = 1024;
static constexpr int OFF_NVS = 2048;
static constexpr int OFF_MF  = 3072;
static constexpr int OFF_MB  = 11792;
static constexpr int OFF_EVS = 20496;
static constexpr int OFF_QV  = 25104;
static constexpr int OFF_AUX = 25120;
static constexpr int SMEM_FLOATS = 25122;
static constexpr int SMEM_INTS   = 2755;
static constexpr int SMEM_BYTES  = (SMEM_FLOATS + SMEM_INTS) * 4;   // 111,508 B

__global__ __launch_bounds__(1024, 1)
void DCG_main_kernel(const float* __restrict__ node_vals,
                     const float* __restrict__ edge_vals,
                     const int* __restrict__ ef_g,
                     const int* __restrict__ et_g,
                     float* __restrict__ out) {
    extern __shared__ float sm[];
    float* q0   = sm + OFF_Q0;
    float* q    = sm + OFF_Q;
    float* nvs  = sm + OFF_NVS;
    float* mf   = sm + OFF_MF;
    float* mb   = sm + OFF_MB;
    float* evs  = sm + OFF_EVS;
    float* qv   = sm + OFF_QV;
    int* si     = (int*)(sm + SMEM_FLOATS);
    int* ef     = si;
    int* et     = si + 512;
    int* ins    = si + 1024;
    int* outs   = si + 1089;
    int* inl    = si + 1154;
    int* outl   = si + 1666;
    int* a_hist = si + 2178;      // 9 * 64
    int* s_bc   = si + 2754;

    const int tid  = threadIdx.x;
    const int b    = blockIdx.x;
    const int warp = tid >> 5;
    const int lane = tid & 31;
    const int j    = lane & 15;
    const int half = lane >> 4;
    const int rA   = lane >> 2;        // 0..7
    const int g4   = (lane & 3) << 2;  // col group base: 0,4,8,12

    // ---- load static data ----
    for (int i = tid; i < N_EDGES; i += 1024) {
        ef[i]   = ef_g[i];
        et[i]   = et_g[i];
        inl[i]  = g_in_list[i];
        outl[i] = g_out_list[i];
    }
    if (tid < N_NODES + 1) { ins[tid] = g_in_start[tid]; outs[tid] = g_out_start[tid]; }

    const float* nv = node_vals + (size_t)b * (N_NODES * N_ACT);
    {
        float raw = nv[tid];
        nvs[tid] = raw;
        float v = raw * INV_N;    // exact (power of two)
        q0[tid] = v;
        q[tid]  = v;
    }
    for (int i = tid; i < N_EDGES * MSG_STRIDE; i += 1024) { mf[i] = 0.0f; mb[i] = 0.0f; }
    __syncthreads();

    // ---- candidate 0: argmax(node_vals) ----
    if (tid < N_NODES) {
        const float* row = nvs + tid * N_ACT;
        int best = 0; float bv = row[0];
        #pragma unroll
        for (int a = 1; a < N_ACT; a++) { float v = row[a]; if (v > bv) { bv = v; best = a; } }
        a_hist[tid] = best;
    }
    __syncthreads();

    const float* ebase = edge_vals + (size_t)b * (N_EDGES * N_ACT * N_ACT);

    // ================= message-passing iterations =================
    for (int it = 0; it < ITERS; it++) {
        // ---- phase 1: per-edge raw messages, register-resident tiles ----
        for (int k = 0; k < 16; k++) {
            int e  = k * 32 + warp;
            int fn = ef[e], tn = et[e];

            // c: lanes 0-15 -> cf[j] = q[fn,j] - mb[e,j]; lanes 16-31 -> ct[j] = q[tn,j] - mf[e,j]
            float c;
            {
                const float* qr = q + (half ? tn : fn) * N_ACT;
                const float* pr = (half ? mf : mb) + e * MSG_STRIDE;
                c = qr[j] - pr[j];
            }

            // tile -> registers: lane holds rows rA (v0) and rA+8 (v1), cols g4..g4+3
            const float4* src = (const float4*)(ebase + (size_t)e * 256);
            float4 v0 = src[lane];
            float4 v1 = src[lane + 32];

            // distribute c (shuffles also act as convergence before in-place stores)
            float cfA = __shfl_sync(0xffffffffu, c, rA);
            float cfB = __shfl_sync(0xffffffffu, c, rA + 8);
            float ct0 = __shfl_sync(0xffffffffu, c, 16 + g4 + 0);
            float ct1 = __shfl_sync(0xffffffffu, c, 16 + g4 + 1);
            float ct2 = __shfl_sync(0xffffffffu, c, 16 + g4 + 2);
            float ct3 = __shfl_sync(0xffffffffu, c, 16 + g4 + 3);

            // forward (column max) partials: pf[k] over rows rA, rA+8 for col g4+k
            float pf0 = fmaxf(fmaf(v0.x, INV_E, cfA), fmaf(v1.x, INV_E, cfB));
            float pf1 = fmaxf(fmaf(v0.y, INV_E, cfA), fmaf(v1.y, INV_E, cfB));
            float pf2 = fmaxf(fmaf(v0.z, INV_E, cfA), fmaf(v1.z, INV_E, cfB));
            float pf3 = fmaxf(fmaf(v0.w, INV_E, cfA), fmaf(v1.w, INV_E, cfB));

            // backward (row max) partials over this lane's 4 columns
            float pbA = fmaxf(fmaxf(fmaf(v0.x, INV_E, ct0), fmaf(v0.y, INV_E, ct1)),
                              fmaxf(fmaf(v0.z, INV_E, ct2), fmaf(v0.w, INV_E, ct3)));
            float pbB = fmaxf(fmaxf(fmaf(v1.x, INV_E, ct0), fmaf(v1.y, INV_E, ct1)),
                              fmaxf(fmaf(v1.z, INV_E, ct2), fmaf(v1.w, INV_E, ct3)));

            // reduce pf over the 8 lanes sharing a col group (rows 0..15)
            #pragma unroll
            for (int d = 4; d <= 16; d <<= 1) {
                pf0 = fmaxf(pf0, __shfl_xor_sync(0xffffffffu, pf0, d));
                pf1 = fmaxf(pf1, __shfl_xor_sync(0xffffffffu, pf1, d));
                pf2 = fmaxf(pf2, __shfl_xor_sync(0xffffffffu, pf2, d));
                pf3 = fmaxf(pf3, __shfl_xor_sync(0xffffffffu, pf3, d));
            }
            // reduce pb over the 4 lanes sharing a row (cols 0..15)
            #pragma unroll
            for (int d = 1; d <= 2; d <<= 1) {
                pbA = fmaxf(pbA, __shfl_xor_sync(0xffffffffu, pbA, d));
                pbB = fmaxf(pbB, __shfl_xor_sync(0xffffffffu, pbB, d));
            }

            // store raw (un-normalized) messages in place
            if (lane < 4) {
                float* d = mf + e * MSG_STRIDE + (lane << 2);
                d[0] = pf0; d[1] = pf1; d[2] = pf2; d[3] = pf3;
            }
            if ((lane & 3) == 0) {
                mb[e * MSG_STRIDE + rA]     = pbA;
                mb[e * MSG_STRIDE + rA + 8] = pbB;
            }
        }
        __syncthreads();

        // ---- phase 1b: subtract per-message mean (STRICT in-order sum) ----
        {
            int e  = tid >> 1;
            float* row = ((tid & 1) ? mb : mf) + e * MSG_STRIDE;
            float v[16];
            #pragma unroll
            for (int i = 0; i < 16; i++) v[i] = row[i];
            float s = v[0];
            #pragma unroll
            for (int i = 1; i < 16; i++) s += v[i];
            float mean = s * INV_A;
            #pragma unroll
            for (int i = 0; i < 16; i++) row[i] = v[i] - mean;
        }
        __syncthreads();

        // ---- phase 2: q = q0 + scatter(mf by to) + scatter(mb by from), ascending edge order ----
        {
            int n = tid >> 4, a = tid & 15;
            float acc = q0[tid];
            int s0 = ins[n], s1 = ins[n + 1];
            for (int kk = s0; kk < s1; kk++) acc += mf[inl[kk] * MSG_STRIDE + a];
            s0 = outs[n]; s1 = outs[n + 1];
            for (int kk = s0; kk < s1; kk++) acc += mb[outl[kk] * MSG_STRIDE + a];
            q[tid] = acc;
        }
        __syncthreads();

        // ---- phase 3: record candidate argmax (first-max, like jnp.argmax) ----
        if (tid < N_NODES) {
            const float* row = q + tid * N_ACT;
            int best = 0; float bv = row[0];
            #pragma unroll
            for (int a = 1; a < N_ACT; a++) { float v = row[a]; if (v > bv) { bv = v; best = a; } }
            a_hist[(it + 1) * N_NODES + tid] = best;
        }
        __syncthreads();
    }

    // ================= deferred evals: 9 candidates in parallel =================
    // stage edge values for every (candidate, edge)
    for (int idx = tid; idx < 9 * N_EDGES; idx += 1024) {
        int c = idx >> 9, e = idx & 511;
        int af = a_hist[c * N_NODES + ef[e]];
        int at = a_hist[c * N_NODES + et[e]];
        evs[idx] = ebase[(size_t)e * 256 + af * 16 + at];
    }
    __syncthreads();
    // strict in-order sums, one lane per candidate (XLA-CPU sequential order)
    if (tid < 9) {
        const float* ev = evs + tid * N_EDGES;
        float es = 0.0f;
        #pragma unroll 8
        for (int e = 0; e < N_EDGES; e++) es += ev[e];
        const int* ah = a_hist + tid * N_NODES;
        float ns = 0.0f;
        #pragma unroll 8
        for (int n = 0; n < N_NODES; n++) ns += nvs[n * N_ACT + ah[n]];
        qv[tid] = ns * INV_N + es * INV_E;
    }
    __syncthreads();
    // sequential best-so-far (matches per-iteration q_val > q_max updates)
    if (tid == 0) {
        float qm = qv[0]; int bc = 0;
        #pragma unroll
        for (int i = 1; i < 9; i++) { if (qv[i] > qm) { qm = qv[i]; bc = i; } }
        sm[OFF_AUX] = qm;
        *s_bc = bc;
    }
    __syncthreads();

    // ---- output: q_max[512] then a_max[512*64] (as float) ----
    if (tid == 0) out[b] = sm[OFF_AUX];
    if (tid < N_NODES) out[N_BATCH + b * N_NODES + tid] = (float)a_hist[(*s_bc) * N_NODES + tid];
}

extern "C" void kernel_launch(void* const* d_in, const int* in_sizes, int n_in,
                              void* d_out, int out_size) {
    const float* node_vals = (const float*)d_in[0];
    const float* edge_vals = (const float*)d_in[1];
    const int*   ef        = (const int*)d_in[2];
    const int*   et        = (const int*)d_in[3];
    float*       out       = (float*)d_out;

    static bool attr_set = false;
    if (!attr_set) {
        cudaFuncSetAttribute(DCG_main_kernel,
                             cudaFuncAttributeMaxDynamicSharedMemorySize, SMEM_BYTES);
        attr_set = true;
    }

    DCG_prep_kernel<<<1, 128>>>(ef, et);
    DCG_main_kernel<<<N_BATCH, 1024, SMEM_BYTES>>>(node_vals, edge_vals, ef, et, out);
}

// round 6
// speedup vs baseline: 2.7709x; 1.2624x over previous
#include <cuda_runtime.h>
#include <cstdint>

#define N_NODES 64
#define N_EDGES 512
#define N_ACT   16
#define ITERS   8
#define N_BATCH 512
#define MSG_STRIDE 17   // padded row stride for mf/mb (bank-conflict-free column access)

static constexpr float INV_E = 1.0f / 512.0f;
static constexpr float INV_N = 1.0f / 64.0f;
static constexpr float INV_A = 1.0f / 16.0f;

// -------- adjacency (batch-independent), built deterministically per launch --------
__device__ int g_in_start[N_NODES + 1];
__device__ int g_out_start[N_NODES + 1];
__device__ int g_in_list[N_EDGES];
__device__ int g_out_list[N_EDGES];

__global__ void DCG_prep_kernel(const int* __restrict__ ef_g, const int* __restrict__ et_g) {
    __shared__ int sf[N_EDGES], st[N_EDGES];
    __shared__ int cin[N_NODES], cout[N_NODES];
    int tid = threadIdx.x;
    for (int e = tid; e < N_EDGES; e += blockDim.x) { sf[e] = ef_g[e]; st[e] = et_g[e]; }
    __syncthreads();
    if (tid < N_NODES) {
        int n = tid, c = 0;
        for (int e = 0; e < N_EDGES; e++) if (st[e] == n) c++;
        cin[n] = c;
    } else if (tid < 2 * N_NODES) {
        int n = tid - N_NODES, c = 0;
        for (int e = 0; e < N_EDGES; e++) if (sf[e] == n) c++;
        cout[n] = c;
    }
    __syncthreads();
    if (tid == 0) {
        int s = 0;
        for (int n = 0; n < N_NODES; n++) { g_in_start[n] = s; s += cin[n]; }
        g_in_start[N_NODES] = s;
    } else if (tid == 1) {
        int s = 0;
        for (int n = 0; n < N_NODES; n++) { g_out_start[n] = s; s += cout[n]; }
        g_out_start[N_NODES] = s;
    }
    __syncthreads();
    if (tid < N_NODES) {
        int n = tid, p = g_in_start[n];
        for (int e = 0; e < N_EDGES; e++) if (st[e] == n) g_in_list[p++] = e;
    } else if (tid < 2 * N_NODES) {
        int n = tid - N_NODES, p = g_out_start[n];
        for (int e = 0; e < N_EDGES; e++) if (sf[e] == n) g_out_list[p++] = e;
    }
}

// -------- shared memory layout --------
static constexpr int OFF_Q0  = 0;
static constexpr int OFF_Q   = 1024;
static constexpr int OFF_NVS = 2048;
static constexpr int OFF_MF  = 3072;
static constexpr int OFF_MB  = 11792;
static constexpr int OFF_EVS = 20496;
static constexpr int OFF_QV  = 25104;
static constexpr int OFF_AUX = 25120;
static constexpr int SMEM_FLOATS = 25122;
static constexpr int SMEM_INTS   = 2755;
static constexpr int SMEM_BYTES  = (SMEM_FLOATS + SMEM_INTS) * 4;   // 111,508 B

__global__ __launch_bounds__(1024, 1)
void DCG_main_kernel(const float* __restrict__ node_vals,
                     const float* __restrict__ edge_vals,
                     const int* __restrict__ ef_g,
                     const int* __restrict__ et_g,
                     float* __restrict__ out) {
    extern __shared__ float sm[];
    float* q0   = sm + OFF_Q0;
    float* q    = sm + OFF_Q;
    float* nvs  = sm + OFF_NVS;
    float* mf   = sm + OFF_MF;
    float* mb   = sm + OFF_MB;
    float* evs  = sm + OFF_EVS;
    float* qv   = sm + OFF_QV;
    int* si     = (int*)(sm + SMEM_FLOATS);
    int* ef     = si;
    int* et     = si + 512;
    int* ins    = si + 1024;
    int* outs   = si + 1089;
    int* inl    = si + 1154;
    int* outl   = si + 1666;
    int* a_hist = si + 2178;      // 9 * 64
    int* s_bc   = si + 2754;

    const int tid  = threadIdx.x;
    const int b    = blockIdx.x;
    const int warp = tid >> 5;
    const int lane = tid & 31;
    const int h    = lane & 15;        // id within half-warp
    const int hw   = lane >> 4;        // which edge of the pair
    const int r0   = h >> 2;           // base row (rows r0, r0+4, r0+8, r0+12)
    const int c4   = (h & 3) << 2;     // base col (cols c4..c4+3)
    const int base16 = lane & 16;

    // ---- load static data ----
    for (int i = tid; i < N_EDGES; i += 1024) {
        ef[i]   = ef_g[i];
        et[i]   = et_g[i];
        inl[i]  = g_in_list[i];
        outl[i] = g_out_list[i];
    }
    if (tid < N_NODES + 1) { ins[tid] = g_in_start[tid]; outs[tid] = g_out_start[tid]; }

    const float* nv = node_vals + (size_t)b * (N_NODES * N_ACT);
    {
        float raw = nv[tid];
        nvs[tid] = raw;
        float v = raw * INV_N;    // exact (power of two)
        q0[tid] = v;
        q[tid]  = v;
    }
    for (int i = tid; i < N_EDGES * MSG_STRIDE; i += 1024) { mf[i] = 0.0f; mb[i] = 0.0f; }
    __syncthreads();

    // ---- candidate 0: argmax(node_vals) ----
    if (tid < N_NODES) {
        const float* row = nvs + tid * N_ACT;
        int best = 0; float bv = row[0];
        #pragma unroll
        for (int a = 1; a < N_ACT; a++) { float v = row[a]; if (v > bv) { bv = v; best = a; } }
        a_hist[tid] = best;
    }
    __syncthreads();

    const float* ebase = edge_vals + (size_t)b * (N_EDGES * N_ACT * N_ACT);

    // ================= message-passing iterations =================
    for (int it = 0; it < ITERS; it++) {
        // ---- phase 1: half-warp per edge, register-resident tiles ----
        for (int k = 0; k < 8; k++) {
            const int e  = k * 64 + warp * 2 + hw;
            const int fn = ef[e], tn = et[e];

            // per-lane c values: c1 = cf[h] = q[fn,h]-mb[e,h]; c2 = ct[h] = q[tn,h]-mf[e,h]
            float c1 = q[fn * N_ACT + h] - mb[e * MSG_STRIDE + h];
            float c2 = q[tn * N_ACT + h] - mf[e * MSG_STRIDE + h];

            // tile -> registers: lane holds rows {r0,r0+4,r0+8,r0+12} x cols {c4..c4+3}
            const float4* src4 = (const float4*)(ebase + (size_t)e * 256);
            float4 v0 = src4[h];
            float4 v1 = src4[h + 16];
            float4 v2 = src4[h + 32];
            float4 v3 = src4[h + 48];

            // distribute c (8 shuffles cover both edges of the warp)
            float cf0 = __shfl_sync(0xffffffffu, c1, base16 | r0);
            float cf1 = __shfl_sync(0xffffffffu, c1, base16 | (r0 + 4));
            float cf2 = __shfl_sync(0xffffffffu, c1, base16 | (r0 + 8));
            float cf3 = __shfl_sync(0xffffffffu, c1, base16 | (r0 + 12));
            float ct0 = __shfl_sync(0xffffffffu, c2, base16 | c4);
            float ct1 = __shfl_sync(0xffffffffu, c2, base16 | (c4 + 1));
            float ct2 = __shfl_sync(0xffffffffu, c2, base16 | (c4 + 2));
            float ct3 = __shfl_sync(0xffffffffu, c2, base16 | (c4 + 3));

            // forward (column max) partials over the 4 in-register rows
            float pf0 = fmaxf(fmaxf(fmaf(v0.x, INV_E, cf0), fmaf(v1.x, INV_E, cf1)),
                              fmaxf(fmaf(v2.x, INV_E, cf2), fmaf(v3.x, INV_E, cf3)));
            float pf1 = fmaxf(fmaxf(fmaf(v0.y, INV_E, cf0), fmaf(v1.y, INV_E, cf1)),
                              fmaxf(fmaf(v2.y, INV_E, cf2), fmaf(v3.y, INV_E, cf3)));
            float pf2 = fmaxf(fmaxf(fmaf(v0.z, INV_E, cf0), fmaf(v1.z, INV_E, cf1)),
                              fmaxf(fmaf(v2.z, INV_E, cf2), fmaf(v3.z, INV_E, cf3)));
            float pf3 = fmaxf(fmaxf(fmaf(v0.w, INV_E, cf0), fmaf(v1.w, INV_E, cf1)),
                              fmaxf(fmaf(v2.w, INV_E, cf2), fmaf(v3.w, INV_E, cf3)));

            // backward (row max) partials over the 4 in-register cols
            float pb0 = fmaxf(fmaxf(fmaf(v0.x, INV_E, ct0), fmaf(v0.y, INV_E, ct1)),
                              fmaxf(fmaf(v0.z, INV_E, ct2), fmaf(v0.w, INV_E, ct3)));
            float pb1 = fmaxf(fmaxf(fmaf(v1.x, INV_E, ct0), fmaf(v1.y, INV_E, ct1)),
                              fmaxf(fmaf(v1.z, INV_E, ct2), fmaf(v1.w, INV_E, ct3)));
            float pb2 = fmaxf(fmaxf(fmaf(v2.x, INV_E, ct0), fmaf(v2.y, INV_E, ct1)),
                              fmaxf(fmaf(v2.z, INV_E, ct2), fmaf(v2.w, INV_E, ct3)));
            float pb3 = fmaxf(fmaxf(fmaf(v3.x, INV_E, ct0), fmaf(v3.y, INV_E, ct1)),
                              fmaxf(fmaf(v3.z, INV_E, ct2), fmaf(v3.w, INV_E, ct3)));

            // column reduce over lanes sharing (h&3): xor 4, 8 (stays within half)
            #pragma unroll
            for (int d = 4; d <= 8; d <<= 1) {
                pf0 = fmaxf(pf0, __shfl_xor_sync(0xffffffffu, pf0, d));
                pf1 = fmaxf(pf1, __shfl_xor_sync(0xffffffffu, pf1, d));
                pf2 = fmaxf(pf2, __shfl_xor_sync(0xffffffffu, pf2, d));
                pf3 = fmaxf(pf3, __shfl_xor_sync(0xffffffffu, pf3, d));
            }
            // row reduce over lanes sharing r0: xor 1, 2
            #pragma unroll
            for (int d = 1; d <= 2; d <<= 1) {
                pb0 = fmaxf(pb0, __shfl_xor_sync(0xffffffffu, pb0, d));
                pb1 = fmaxf(pb1, __shfl_xor_sync(0xffffffffu, pb1, d));
                pb2 = fmaxf(pb2, __shfl_xor_sync(0xffffffffu, pb2, d));
                pb3 = fmaxf(pb3, __shfl_xor_sync(0xffffffffu, pb3, d));
            }

            // store raw (un-normalized) messages
            if (h < 4) {   // lane h holds cols 4h..4h+3 (h&3 == h)
                float* d = mf + e * MSG_STRIDE + (h << 2);
                d[0] = pf0; d[1] = pf1; d[2] = pf2; d[3] = pf3;
            }
            if ((h & 3) == 0) {   // lane holds rows r0, r0+4, r0+8, r0+12
                float* d = mb + e * MSG_STRIDE + r0;
                d[0] = pb0; d[4] = pb1; d[8] = pb2; d[12] = pb3;
            }
        }
        __syncthreads();

        // ---- phase 1b: subtract per-message mean (STRICT in-order sum) ----
        {
            int e  = tid >> 1;
            float* row = ((tid & 1) ? mb : mf) + e * MSG_STRIDE;
            float v[16];
            #pragma unroll
            for (int i = 0; i < 16; i++) v[i] = row[i];
            float s = v[0];
            #pragma unroll
            for (int i = 1; i < 16; i++) s += v[i];
            float mean = s * INV_A;
            #pragma unroll
            for (int i = 0; i < 16; i++) row[i] = v[i] - mean;
        }
        __syncthreads();

        // ---- phase 2: q = q0 + scatter(mf by to) + scatter(mb by from), ascending edge order ----
        {
            int n = tid >> 4, a = tid & 15;
            float acc = q0[tid];
            int s0 = ins[n], s1 = ins[n + 1];
            for (int kk = s0; kk < s1; kk++) acc += mf[inl[kk] * MSG_STRIDE + a];
            s0 = outs[n]; s1 = outs[n + 1];
            for (int kk = s0; kk < s1; kk++) acc += mb[outl[kk] * MSG_STRIDE + a];
            q[tid] = acc;
        }
        __syncthreads();

        // ---- phase 3: record candidate argmax (first-max, like jnp.argmax) ----
        if (tid < N_NODES) {
            const float* row = q + tid * N_ACT;
            int best = 0; float bv = row[0];
            #pragma unroll
            for (int a = 1; a < N_ACT; a++) { float v = row[a]; if (v > bv) { bv = v; best = a; } }
            a_hist[(it + 1) * N_NODES + tid] = best;
        }
        __syncthreads();
    }

    // ================= deferred evals: 9 candidates in parallel =================
    for (int idx = tid; idx < 9 * N_EDGES; idx += 1024) {
        int c = idx >> 9, e = idx & 511;
        int af = a_hist[c * N_NODES + ef[e]];
        int at = a_hist[c * N_NODES + et[e]];
        evs[idx] = ebase[(size_t)e * 256 + af * 16 + at];
    }
    __syncthreads();
    // strict in-order sums, one lane per candidate (XLA-CPU sequential order)
    if (tid < 9) {
        const float* ev = evs + tid * N_EDGES;
        float es = 0.0f;
        #pragma unroll 8
        for (int e = 0; e < N_EDGES; e++) es += ev[e];
        const int* ah = a_hist + tid * N_NODES;
        float ns = 0.0f;
        #pragma unroll 8
        for (int n = 0; n < N_NODES; n++) ns += nvs[n * N_ACT + ah[n]];
        qv[tid] = ns * INV_N + es * INV_E;
    }
    __syncthreads();
    if (tid == 0) {
        float qm = qv[0]; int bc = 0;
        #pragma unroll
        for (int i = 1; i < 9; i++) { if (qv[i] > qm) { qm = qv[i]; bc = i; } }
        sm[OFF_AUX] = qm;
        *s_bc = bc;
    }
    __syncthreads();

    // ---- output: q_max[512] then a_max[512*64] (as float) ----
    if (tid == 0) out[b] = sm[OFF_AUX];
    if (tid < N_NODES) out[N_BATCH + b * N_NODES + tid] = (float)a_hist[(*s_bc) * N_NODES + tid];
}

extern "C" void kernel_launch(void* const* d_in, const int* in_sizes, int n_in,
                              void* d_out, int out_size) {
    const float* node_vals = (const float*)d_in[0];
    const float* edge_vals = (const float*)d_in[1];
    const int*   ef        = (const int*)d_in[2];
    const int*   et        = (const int*)d_in[3];
    float*       out       = (float*)d_out;

    static bool attr_set = false;
    if (!attr_set) {
        cudaFuncSetAttribute(DCG_main_kernel,
                             cudaFuncAttributeMaxDynamicSharedMemorySize, SMEM_BYTES);
        attr_set = true;
    }

    DCG_prep_kernel<<<1, 128>>>(ef, et);
    DCG_main_kernel<<<N_BATCH, 1024, SMEM_BYTES>>>(node_vals, edge_vals, ef, et, out);
}

// round 8
// speedup vs baseline: 3.0754x; 1.1099x over previous
#include <cuda_runtime.h>
#include <cstdint>

#define N_NODES 64
#define N_EDGES 512
#define N_ACT   16
#define ITERS   8
#define N_BATCH 512
#define MSG_STRIDE 17   // padded row stride for mf/mb (bank-conflict-free column access)

static constexpr float INV_E = 1.0f / 512.0f;
static constexpr float INV_N = 1.0f / 64.0f;
static constexpr float INV_A = 1.0f / 16.0f;

// 4x4 register transpose among 4 lanes at xor-distances d0 (rank bit0), d1 (rank bit1).
// m = rank of this lane (0..3). After: p[k] = original p[m] of rank-k lane.
__device__ __forceinline__ void xpose4(float& p0, float& p1, float& p2, float& p3,
                                       int m, int d0, int d1) {
    float t;
    t = __shfl_xor_sync(0xffffffffu, (m & 1) ? p0 : p1, d0);
    if (m & 1) p0 = t; else p1 = t;
    t = __shfl_xor_sync(0xffffffffu, (m & 1) ? p2 : p3, d0);
    if (m & 1) p2 = t; else p3 = t;
    t = __shfl_xor_sync(0xffffffffu, (m & 2) ? p0 : p2, d1);
    if (m & 2) p0 = t; else p2 = t;
    t = __shfl_xor_sync(0xffffffffu, (m & 2) ? p1 : p3, d1);
    if (m & 2) p1 = t; else p3 = t;
}

// -------- adjacency (batch-independent), built deterministically per launch --------
__device__ int g_in_start[N_NODES + 1];
__device__ int g_out_start[N_NODES + 1];
__device__ int g_in_list[N_EDGES];
__device__ int g_out_list[N_EDGES];

__global__ void DCG_prep_kernel(const int* __restrict__ ef_g, const int* __restrict__ et_g) {
    __shared__ int sf[N_EDGES], st[N_EDGES];
    __shared__ int cin[N_NODES], cout[N_NODES];
    int tid = threadIdx.x;
    for (int e = tid; e < N_EDGES; e += blockDim.x) { sf[e] = ef_g[e]; st[e] = et_g[e]; }
    __syncthreads();
    if (tid < N_NODES) {
        int n = tid, c = 0;
        for (int e = 0; e < N_EDGES; e++) if (st[e] == n) c++;
        cin[n] = c;
    } else if (tid < 2 * N_NODES) {
        int n = tid - N_NODES, c = 0;
        for (int e = 0; e < N_EDGES; e++) if (sf[e] == n) c++;
        cout[n] = c;
    }
    __syncthreads();
    if (tid == 0) {
        int s = 0;
        for (int n = 0; n < N_NODES; n++) { g_in_start[n] = s; s += cin[n]; }
        g_in_start[N_NODES] = s;
    } else if (tid == 1) {
        int s = 0;
        for (int n = 0; n < N_NODES; n++) { g_out_start[n] = s; s += cout[n]; }
        g_out_start[N_NODES] = s;
    }
    __syncthreads();
    if (tid < N_NODES) {
        int n = tid, p = g_in_start[n];
        for (int e = 0; e < N_EDGES; e++) if (st[e] == n) g_in_list[p++] = e;
    } else if (tid < 2 * N_NODES) {
        int n = tid - N_NODES, p = g_out_start[n];
        for (int e = 0; e < N_EDGES; e++) if (sf[e] == n) g_out_list[p++] = e;
    }
}

// -------- shared memory layout --------
static constexpr int OFF_Q0  = 0;
static constexpr int OFF_Q   = 1024;
static constexpr int OFF_NVS = 2048;
static constexpr int OFF_MF  = 3072;
static constexpr int OFF_MB  = 11792;
static constexpr int OFF_EVS = 20496;
static constexpr int OFF_QV  = 25104;
static constexpr int OFF_AUX = 25120;
static constexpr int SMEM_FLOATS = 25122;
static constexpr int SMEM_INTS   = 2755;
static constexpr int SMEM_BYTES  = (SMEM_FLOATS + SMEM_INTS) * 4;   // 111,508 B

__global__ __launch_bounds__(1024, 1)
void DCG_main_kernel(const float* __restrict__ node_vals,
                     const float* __restrict__ edge_vals,
                     const int* __restrict__ ef_g,
                     const int* __restrict__ et_g,
                     float* __restrict__ out) {
    extern __shared__ float sm[];
    float* q0   = sm + OFF_Q0;
    float* q    = sm + OFF_Q;
    float* nvs  = sm + OFF_NVS;
    float* mf   = sm + OFF_MF;
    float* mb   = sm + OFF_MB;
    float* evs  = sm + OFF_EVS;
    float* qv   = sm + OFF_QV;
    int* si     = (int*)(sm + SMEM_FLOATS);
    int* ef     = si;
    int* et     = si + 512;
    int* ins    = si + 1024;
    int* outs   = si + 1089;
    int* inl    = si + 1154;
    int* outl   = si + 1666;
    int* a_hist = si + 2178;      // 9 * 64
    int* s_bc   = si + 2754;

    const int tid  = threadIdx.x;
    const int b    = blockIdx.x;
    const int warp = tid >> 5;
    const int lane = tid & 31;
    const int h    = lane & 15;        // id within half-warp
    const int hw   = lane >> 4;        // which edge of the pair
    const int r0   = h >> 2;           // base row (rows r0, r0+4, r0+8, r0+12)
    const int c4   = (h & 3) << 2;     // base col (cols c4..c4+3)
    const int base16 = lane & 16;
    const int perm = c4 + r0;          // 4*(h&3) + (h>>2): output index this lane stores

    // ---- load static data ----
    for (int i = tid; i < N_EDGES; i += 1024) {
        ef[i]   = ef_g[i];
        et[i]   = et_g[i];
        inl[i]  = g_in_list[i];
        outl[i] = g_out_list[i];
    }
    if (tid < N_NODES + 1) { ins[tid] = g_in_start[tid]; outs[tid] = g_out_start[tid]; }

    const float* nv = node_vals + (size_t)b * (N_NODES * N_ACT);
    {
        float raw = nv[tid];
        nvs[tid] = raw;
        float v = raw * INV_N;    // exact (power of two)
        q0[tid] = v;
        q[tid]  = v;
    }
    for (int i = tid; i < N_EDGES * MSG_STRIDE; i += 1024) { mf[i] = 0.0f; mb[i] = 0.0f; }
    __syncthreads();

    // ---- candidate 0: argmax(node_vals) ----
    if (tid < N_NODES) {
        const float* row = nvs + tid * N_ACT;
        int best = 0; float bv = row[0];
        #pragma unroll
        for (int a = 1; a < N_ACT; a++) { float v = row[a]; if (v > bv) { bv = v; best = a; } }
        a_hist[tid] = best;
    }
    __syncthreads();

    const float* ebase = edge_vals + (size_t)b * (N_EDGES * N_ACT * N_ACT);

    // ================= message-passing iterations =================
    for (int it = 0; it < ITERS; it++) {
        // ---- phase 1: half-warp per edge, register-resident tiles, transpose-reduce ----
        for (int k = 0; k < 8; k++) {
            const int e  = k * 64 + warp * 2 + hw;
            const int fn = ef[e], tn = et[e];

            // per-lane c values: c1 = cf[h] = q[fn,h]-mb[e,h]; c2 = ct[h] = q[tn,h]-mf[e,h]
            float c1 = q[fn * N_ACT + h] - mb[e * MSG_STRIDE + h];
            float c2 = q[tn * N_ACT + h] - mf[e * MSG_STRIDE + h];

            // tile -> registers: lane holds rows {r0,r0+4,r0+8,r0+12} x cols {c4..c4+3}
            const float4* src4 = (const float4*)(ebase + (size_t)e * 256);
            float4 v0 = src4[h];
            float4 v1 = src4[h + 16];
            float4 v2 = src4[h + 32];
            float4 v3 = src4[h + 48];

            // distribute c (8 shuffles, both edges of the warp at once)
            float cf0 = __shfl_sync(0xffffffffu, c1, base16 | r0);
            float cf1 = __shfl_sync(0xffffffffu, c1, base16 | (r0 + 4));
            float cf2 = __shfl_sync(0xffffffffu, c1, base16 | (r0 + 8));
            float cf3 = __shfl_sync(0xffffffffu, c1, base16 | (r0 + 12));
            float ct0 = __shfl_sync(0xffffffffu, c2, base16 | c4);
            float ct1 = __shfl_sync(0xffffffffu, c2, base16 | (c4 + 1));
            float ct2 = __shfl_sync(0xffffffffu, c2, base16 | (c4 + 2));
            float ct3 = __shfl_sync(0xffffffffu, c2, base16 | (c4 + 3));

            // forward (column max) partials over the 4 in-register rows
            float pf0 = fmaxf(fmaxf(fmaf(v0.x, INV_E, cf0), fmaf(v1.x, INV_E, cf1)),
                              fmaxf(fmaf(v2.x, INV_E, cf2), fmaf(v3.x, INV_E, cf3)));
            float pf1 = fmaxf(fmaxf(fmaf(v0.y, INV_E, cf0), fmaf(v1.y, INV_E, cf1)),
                              fmaxf(fmaf(v2.y, INV_E, cf2), fmaf(v3.y, INV_E, cf3)));
            float pf2 = fmaxf(fmaxf(fmaf(v0.z, INV_E, cf0), fmaf(v1.z, INV_E, cf1)),
                              fmaxf(fmaf(v2.z, INV_E, cf2), fmaf(v3.z, INV_E, cf3)));
            float pf3 = fmaxf(fmaxf(fmaf(v0.w, INV_E, cf0), fmaf(v1.w, INV_E, cf1)),
                              fmaxf(fmaf(v2.w, INV_E, cf2), fmaf(v3.w, INV_E, cf3)));

            // backward (row max) partials over the 4 in-register cols
            float pb0 = fmaxf(fmaxf(fmaf(v0.x, INV_E, ct0), fmaf(v0.y, INV_E, ct1)),
                              fmaxf(fmaf(v0.z, INV_E, ct2), fmaf(v0.w, INV_E, ct3)));
            float pb1 = fmaxf(fmaxf(fmaf(v1.x, INV_E, ct0), fmaf(v1.y, INV_E, ct1)),
                              fmaxf(fmaf(v1.z, INV_E, ct2), fmaf(v1.w, INV_E, ct3)));
            float pb2 = fmaxf(fmaxf(fmaf(v2.x, INV_E, ct0), fmaf(v2.y, INV_E, ct1)),
                              fmaxf(fmaf(v2.z, INV_E, ct2), fmaf(v2.w, INV_E, ct3)));
            float pb3 = fmaxf(fmaxf(fmaf(v3.x, INV_E, ct0), fmaf(v3.y, INV_E, ct1)),
                              fmaxf(fmaf(v3.z, INV_E, ct2), fmaf(v3.w, INV_E, ct3)));

            // transpose-reduce pf: lanes {g, g+4, g+8, g+12}, rank = h>>2
            xpose4(pf0, pf1, pf2, pf3, r0, 4, 8);
            float rf = fmaxf(fmaxf(pf0, pf1), fmaxf(pf2, pf3));
            // transpose-reduce pb: lanes {4r..4r+3}, rank = h&3
            xpose4(pb0, pb1, pb2, pb3, h & 3, 1, 2);
            float rb = fmaxf(fmaxf(pb0, pb1), fmaxf(pb2, pb3));

            // lane h stores output index perm = 4*(h&3) + (h>>2) for both directions
            mf[e * MSG_STRIDE + perm] = rf;   // col max -> mf[e, perm]
            mb[e * MSG_STRIDE + perm] = rb;   // row max -> mb[e, perm]
        }
        __syncthreads();

        // ---- phase 1b: subtract per-message mean (STRICT in-order sum) ----
        {
            int e  = tid >> 1;
            float* row = ((tid & 1) ? mb : mf) + e * MSG_STRIDE;
            float v[16];
            #pragma unroll
            for (int i = 0; i < 16; i++) v[i] = row[i];
            float s = v[0];
            #pragma unroll
            for (int i = 1; i < 16; i++) s += v[i];
            float mean = s * INV_A;
            #pragma unroll
            for (int i = 0; i < 16; i++) row[i] = v[i] - mean;
        }
        __syncthreads();

        // ---- phase 2: q = q0 + scatter(mf by to) + scatter(mb by from), ascending edge order ----
        {
            int n = tid >> 4, a = tid & 15;
            float acc = q0[tid];
            int s0 = ins[n], s1 = ins[n + 1];
            for (int kk = s0; kk < s1; kk++) acc += mf[inl[kk] * MSG_STRIDE + a];
            s0 = outs[n]; s1 = outs[n + 1];
            for (int kk = s0; kk < s1; kk++) acc += mb[outl[kk] * MSG_STRIDE + a];
            q[tid] = acc;
        }
        __syncthreads();

        // ---- phase 3: record candidate argmax (first-max, like jnp.argmax) ----
        if (tid < N_NODES) {
            const float* row = q + tid * N_ACT;
            int best = 0; float bv = row[0];
            #pragma unroll
            for (int a = 1; a < N_ACT; a++) { float v = row[a]; if (v > bv) { bv = v; best = a; } }
            a_hist[(it + 1) * N_NODES + tid] = best;
        }
        __syncthreads();
    }

    // ================= deferred evals: 9 candidates in parallel =================
    for (int idx = tid; idx < 9 * N_EDGES; idx += 1024) {
        int c = idx >> 9, e = idx & 511;
        int af = a_hist[c * N_NODES + ef[e]];
        int at = a_hist[c * N_NODES + et[e]];
        evs[idx] = ebase[(size_t)e * 256 + af * 16 + at];
    }
    __syncthreads();
    // strict in-order sums, one lane per candidate (XLA-CPU sequential order)
    if (tid < 9) {
        const float* ev = evs + tid * N_EDGES;
        float es = 0.0f;
        #pragma unroll 8
        for (int e = 0; e < N_EDGES; e++) es += ev[e];
        const int* ah = a_hist + tid * N_NODES;
        float ns = 0.0f;
        #pragma unroll 8
        for (int n = 0; n < N_NODES; n++) ns += nvs[n * N_ACT + ah[n]];
        qv[tid] = ns * INV_N + es * INV_E;
    }
    __syncthreads();
    if (tid == 0) {
        float qm = qv[0]; int bc = 0;
        #pragma unroll
        for (int i = 1; i < 9; i++) { if (qv[i] > qm) { qm = qv[i]; bc = i; } }
        sm[OFF_AUX] = qm;
        *s_bc = bc;
    }
    __syncthreads();

    // ---- output: q_max[512] then a_max[512*64] (as float) ----
    if (tid == 0) out[b] = sm[OFF_AUX];
    if (tid < N_NODES) out[N_BATCH + b * N_NODES + tid] = (float)a_hist[(*s_bc) * N_NODES + tid];
}

extern "C" void kernel_launch(void* const* d_in, const int* in_sizes, int n_in,
                              void* d_out, int out_size) {
    const float* node_vals = (const float*)d_in[0];
    const float* edge_vals = (const float*)d_in[1];
    const int*   ef        = (const int*)d_in[2];
    const int*   et        = (const int*)d_in[3];
    float*       out       = (float*)d_out;

    static bool attr_set = false;
    if (!attr_set) {
        cudaFuncSetAttribute(DCG_main_kernel,
                             cudaFuncAttributeMaxDynamicSharedMemorySize, SMEM_BYTES);
        attr_set = true;
    }

    DCG_prep_kernel<<<1, 128>>>(ef, et);
    DCG_main_kernel<<<N_BATCH, 1024, SMEM_BYTES>>>(node_vals, edge_vals, ef, et, out);
}